// round 15
// baseline (speedup 1.0000x reference)
#include <cuda_runtime.h>
#include <cuda_bf16.h>
#include <cstdint>

// ---------------- scratch (no runtime allocation) ----------------
__device__ __align__(16) unsigned int  g_tgt2[8 * 4096 * 16];        // 2 MiB: 2-bit classes [b][l][ky]
__device__ __align__(16) __nv_bfloat16 g_uconv[32 * 256 * 256];      // 4 MiB: [b*4+c][m][k]
__device__ double g_acc;
__device__ int    g_is32;

// ---------------- helpers ----------------
__device__ __forceinline__ uint32_t smem_u32(const void* p) {
    uint32_t a;
    asm("{ .reg .u64 t; cvta.to.shared.u64 t, %1; cvt.u32.u64 %0, t; }" : "=r"(a) : "l"(p));
    return a;
}

#define ST4(addr, a, b, c, d) \
    asm volatile("st.shared.v4.b32 [%0], {%1,%2,%3,%4};" :: "r"(addr), "r"(a), "r"(b), "r"(c), "r"(d) : "memory")

__device__ __forceinline__ void ldsm_x4_t(uint32_t& r0, uint32_t& r1, uint32_t& r2, uint32_t& r3, uint32_t addr) {
    asm volatile("ldmatrix.sync.aligned.m8n8.x4.trans.shared.b16 {%0,%1,%2,%3}, [%4];"
                 : "=r"(r0), "=r"(r1), "=r"(r2), "=r"(r3) : "r"(addr));
}
__device__ __forceinline__ uint32_t lds_u32(uint32_t addr) {
    uint32_t v;
    asm volatile("ld.shared.b32 %0, [%1];" : "=r"(v) : "r"(addr));
    return v;
}
__device__ __forceinline__ void mma_bf16(float& c0, float& c1, float& c2, float& c3,
                                         uint32_t a0, uint32_t a1, uint32_t a2, uint32_t a3,
                                         uint32_t b0, uint32_t b1) {
    asm volatile("mma.sync.aligned.m16n8k16.row.col.f32.bf16.bf16.f32 "
                 "{%0,%1,%2,%3}, {%4,%5,%6,%7}, {%8,%9}, {%0,%1,%2,%3};"
                 : "+f"(c0), "+f"(c1), "+f"(c2), "+f"(c3)
                 : "r"(a0), "r"(a1), "r"(a2), "r"(a3), "r"(b0), "r"(b1));
}
// match-mask: bit 2j of result set iff 2-bit code j of w equals c
__device__ __forceinline__ uint32_t match_u(uint32_t w, uint32_t c) {
    uint32_t t = w ^ (0x55555555u * c);
    return (~t) & ((~t) >> 1) & 0x55555555u;
}
// bf16x2 A fragment {k=base/2, k=base/2+1} from match word (bit positions base, base+2)
__device__ __forceinline__ uint32_t apair(uint32_t u, uint32_t base) {
    return (((u >> base) & 1u) * 0x3F80u) | (((u >> (base + 2)) & 1u) * 0x3F800000u);
}

// ---------------- tiny kernels ----------------
__global__ void zero_kernel() { g_acc = 0.0; g_is32 = 0; }

__global__ void detect_kernel(const unsigned int* __restrict__ t) {
    unsigned int any = 0;
    for (int i = threadIdx.x; i < 8192; i += 256) any |= t[2 * i + 1];
    if (any) g_is32 = 1;   // int32 data: odd words carry real values (nonzero w.h.p.)
}

__global__ void finalize_kernel(float* __restrict__ out) {
    out[0] = (float)(g_acc * (1.0 / 33554432.0));
}

// ---------------- prep: target -> packed 2-bit patch codes + pooled bf16 u_conv ----------------
// grid 128 = 8 b * 16 slabs of 64 rows; 512 threads
__global__ void __launch_bounds__(512) prep_kernel(const void* __restrict__ traw) {
    __shared__ unsigned s_cls[4096];   // [y_local 0..63][x/16], 16 px per word, 2 bits each
    int b = blockIdx.x >> 4, slab = blockIdx.x & 15;

    if (g_is32) {
        const uint4* tb = (const uint4*)((const int*)traw + (((size_t)b) << 20) + (((size_t)slab) << 16));
        for (int w = threadIdx.x; w < 4096; w += 512) {
            int y = w >> 6, xw = w & 63;
            const uint4* p = tb + y * 256 + xw * 4;
            unsigned packed = 0;
#pragma unroll
            for (int i = 0; i < 4; i++) {
                uint4 v = p[i];
                packed |= (v.x & 3u) << (8 * i);
                packed |= (v.y & 3u) << (8 * i + 2);
                packed |= (v.z & 3u) << (8 * i + 4);
                packed |= (v.w & 3u) << (8 * i + 6);
            }
            s_cls[w] = packed;
        }
    } else {
        const longlong2* tb = (const longlong2*)((const long long*)traw + (((size_t)b) << 20) + (((size_t)slab) << 16));
        for (int w = threadIdx.x; w < 4096; w += 512) {
            int y = w >> 6, xw = w & 63;
            const longlong2* p = tb + y * 512 + xw * 8;
            unsigned packed = 0;
#pragma unroll
            for (int i = 0; i < 8; i++) {
                longlong2 v = p[i];
                packed |= ((unsigned)v.x & 3u) << (4 * i);
                packed |= ((unsigned)v.y & 3u) << (4 * i + 2);
            }
            s_cls[w] = packed;
        }
    }
    __syncthreads();

    // --- tgt2: per patch l, 16 words (one per ky), each word = 16 kx classes ---
    unsigned* outb = g_tgt2 + ((size_t)(b * 4096 + slab * 256)) * 16;
    for (int o = threadIdx.x; o < 4096; o += 512) {
        int ky = o >> 8, l_loc = o & 255;
        int Yl = l_loc >> 6, Xl = l_loc & 63;
        outb[l_loc * 16 + ky] = s_cls[(Yl * 16 + ky) * 64 + Xl];
    }

    // --- u_conv: 4x4 pool of one-hot, written transposed as [bc][m][k] bf16 ---
    for (int o = threadIdx.x; o < 4096; o += 512) {
        int yb = o >> 8, xb = o & 255;          // pooled coords (local row, col)
        unsigned w32 = 0;
#pragma unroll
        for (int rr = 0; rr < 4; rr++) {
            unsigned wd = s_cls[(yb * 4 + rr) * 64 + (xb >> 2)];
            w32 |= ((wd >> (8 * (xb & 3))) & 0xFFu) << (8 * rr);   // 16 codes of this 4x4 block
        }
        int y = slab * 16 + yb;                 // global pooled row 0..255
        int m = ((y >> 4) * 16) + (xb >> 4);
        int k = ((y & 15) * 16) + (xb & 15);
#pragma unroll
        for (unsigned c = 0; c < 4; c++) {
            unsigned t = w32 ^ (0x55555555u * c);
            unsigned u = (~t) & ((~t) >> 1) & 0x55555555u;
            float v = (float)__popc(u) * 0.0625f;
            g_uconv[(((size_t)b * 4 + c) * 256 + m) * 256 + k] = __float2bfloat16(v);
        }
    }
}

// ---------------- GEMM (mma.sync bf16, A expanded from codes) + fused epilogue ----------------
// CTA tile: 128 l x 128 m. smem: A codes (128 rows x 17 u32 padded, 8.5 KB) + B half 64 KB.
#define SM_CODE   0
#define SM_B      9216
#define SM_TOTAL  (9216 + 65536)

__global__ void __launch_bounds__(256, 2) gemm_kernel(const float* __restrict__ att) {
    extern __shared__ char smem[];
    __shared__ float s_ws[8];
    uint32_t sbase = smem_u32(smem);
    int tid = threadIdx.x, wid = tid >> 5, ln = tid & 31;
    int bid = blockIdx.x;
    int mh  = bid & 1;                 // m half (0/1)
    int lt  = (bid >> 1) & 31;         // 128-row l tile
    int bc  = bid >> 6;                // b*4+c

    // prefetch this CTA's 64 KB attentions tile into L2
    const float* atile = att + ((size_t)bc * 4096 + (size_t)lt * 128) * 256 + mh * 128;
    for (int i = tid; i < 512; i += 256)
        asm volatile("prefetch.global.L2 [%0];" :: "l"(atile + (i >> 1) * 256 + (i & 1) * 64));

    // ---- A codes fill: 128 rows x 16 words, padded row stride 17 ----
    {
        int b = bc >> 2;
        int r = tid >> 1, h = tid & 1;
        const uint4* src = (const uint4*)(g_tgt2 + ((size_t)(b * 4096 + lt * 128 + r)) * 16 + h * 8);
        uint4 v0 = src[0], v1 = src[1];
        uint32_t dst = sbase + SM_CODE + (uint32_t)((r * 17 + h * 8) * 4);
        asm volatile("st.shared.b32 [%0], %1;" :: "r"(dst +  0), "r"(v0.x) : "memory");
        asm volatile("st.shared.b32 [%0], %1;" :: "r"(dst +  4), "r"(v0.y) : "memory");
        asm volatile("st.shared.b32 [%0], %1;" :: "r"(dst +  8), "r"(v0.z) : "memory");
        asm volatile("st.shared.b32 [%0], %1;" :: "r"(dst + 12), "r"(v0.w) : "memory");
        asm volatile("st.shared.b32 [%0], %1;" :: "r"(dst + 16), "r"(v1.x) : "memory");
        asm volatile("st.shared.b32 [%0], %1;" :: "r"(dst + 20), "r"(v1.y) : "memory");
        asm volatile("st.shared.b32 [%0], %1;" :: "r"(dst + 24), "r"(v1.z) : "memory");
        asm volatile("st.shared.b32 [%0], %1;" :: "r"(dst + 28), "r"(v1.w) : "memory");
    }

    // ---- B fill: u_conv[bc] rows [mh*128, mh*128+128) (64 KB), rows 512 B, XOR-16B swizzle ----
    {
        const uint4* src = (const uint4*)(g_uconv + (size_t)bc * 65536 + (size_t)mh * 32768);
        for (int idx = tid; idx < 4096; idx += 256) {
            int m = idx >> 5, u = idx & 31;
            uint4 v = src[idx];
            uint32_t addr = sbase + SM_B + (uint32_t)(m * 512) +
                            (((uint32_t)(u * 16)) ^ (uint32_t)((m & 7) << 4));
            ST4(addr, v.x, v.y, v.z, v.w);
        }
    }
    __syncthreads();

    // ---- per-warp tile: 32 l-rows x 64 m-cols ----
    int l_base = (wid & 3) * 32;
    int m_base = (wid >> 2) * 64;      // within CTA's 128 m
    unsigned cc = (unsigned)(bc & 3);

    // A code row addresses: rows g, g+8 (block0), g+16, g+24 (block1); word s at +4s
    uint32_t g = (uint32_t)(ln >> 2);
    uint32_t crow0 = sbase + SM_CODE + (uint32_t)((l_base + g) * 17 * 4);
    uint32_t crow1 = crow0 + 8 * 17 * 4;
    uint32_t crow2 = crow0 + 16 * 17 * 4;
    uint32_t crow3 = crow0 + 24 * 17 * 4;
    uint32_t pb = (uint32_t)((ln & 3) * 4);      // bit base for k pair

    // B ldmatrix bases (validated R11 mapping), mb = m_base
    uint32_t bbase[4], bsw[4];
#pragma unroll
    for (int jj = 0; jj < 4; jj++) {
        int r = m_base + (jj * 2 + (ln >> 4)) * 8 + (ln & 7);
        bbase[jj] = sbase + SM_B + (uint32_t)(r * 512);
        bsw[jj]   = (uint32_t)((r & 7) << 4);
    }
    uint32_t bko = (uint32_t)(((ln >> 3) & 1) * 16);

    float acc[64];
#pragma unroll
    for (int i = 0; i < 64; i++) acc[i] = 0.f;

    uint32_t uw[2][4], bfr[2][16];
    {   // preload s = 0
        uw[0][0] = lds_u32(crow0); uw[0][1] = lds_u32(crow1);
        uw[0][2] = lds_u32(crow2); uw[0][3] = lds_u32(crow3);
#pragma unroll
        for (int jj = 0; jj < 4; jj++)
            ldsm_x4_t(bfr[0][jj * 4 + 0], bfr[0][jj * 4 + 1], bfr[0][jj * 4 + 2], bfr[0][jj * 4 + 3],
                      bbase[jj] + (bko ^ bsw[jj]));
    }

#pragma unroll
    for (int s = 0; s < 16; s++) {
        int cur = s & 1, nxt = cur ^ 1;
        if (s < 15) {
            uint32_t wofs = (uint32_t)((s + 1) * 4);
            uw[nxt][0] = lds_u32(crow0 + wofs); uw[nxt][1] = lds_u32(crow1 + wofs);
            uw[nxt][2] = lds_u32(crow2 + wofs); uw[nxt][3] = lds_u32(crow3 + wofs);
            uint32_t kb = (uint32_t)((s + 1) * 32) + bko;
#pragma unroll
            for (int jj = 0; jj < 4; jj++)
                ldsm_x4_t(bfr[nxt][jj * 4 + 0], bfr[nxt][jj * 4 + 1], bfr[nxt][jj * 4 + 2], bfr[nxt][jj * 4 + 3],
                          bbase[jj] + (kb ^ bsw[jj]));
        }
        // expand A fragments from code words (mma m16n8k16 lane mapping)
        uint32_t u0 = match_u(uw[cur][0], cc), u1 = match_u(uw[cur][1], cc);
        uint32_t u2 = match_u(uw[cur][2], cc), u3 = match_u(uw[cur][3], cc);
        uint32_t a0 = apair(u0, pb),      a1 = apair(u1, pb);
        uint32_t a2 = apair(u0, pb + 16), a3 = apair(u1, pb + 16);
        uint32_t a4 = apair(u2, pb),      a5 = apair(u3, pb);
        uint32_t a6 = apair(u2, pb + 16), a7 = apair(u3, pb + 16);
#pragma unroll
        for (int j = 0; j < 8; j++) {
            uint32_t b0 = bfr[cur][(j >> 1) * 4 + (j & 1) * 2];
            uint32_t b1 = bfr[cur][(j >> 1) * 4 + (j & 1) * 2 + 1];
            mma_bf16(acc[j * 4 + 0], acc[j * 4 + 1], acc[j * 4 + 2], acc[j * 4 + 3],
                     a0, a1, a2, a3, b0, b1);
            mma_bf16(acc[32 + j * 4 + 0], acc[32 + j * 4 + 1], acc[32 + j * 4 + 2], acc[32 + j * 4 + 3],
                     a4, a5, a6, a7, b0, b1);
        }
    }

    // ---- fused epilogue: (att - acc/256)^2 ----
    float wsum = 0.f;
    const float s256 = 1.f / 256.f;
#pragma unroll
    for (int i = 0; i < 2; i++) {
        int R = l_base + i * 16 + (ln >> 2);
#pragma unroll
        for (int j = 0; j < 8; j++) {
            int C = m_base + j * 8 + (ln & 3) * 2;
            float2 t0 = __ldg((const float2*)(atile + (size_t)R * 256 + C));
            float2 t1 = __ldg((const float2*)(atile + (size_t)(R + 8) * 256 + C));
            float* a = &acc[i * 32 + j * 4];
            float d0 = t0.x - a[0] * s256;
            float d1 = t0.y - a[1] * s256;
            float d2 = t1.x - a[2] * s256;
            float d3 = t1.y - a[3] * s256;
            wsum += d0 * d0 + d1 * d1 + d2 * d2 + d3 * d3;
        }
    }

    // ---- reduce: warp -> CTA -> one double atomic per CTA ----
#pragma unroll
    for (int off = 16; off; off >>= 1) wsum += __shfl_xor_sync(0xFFFFFFFFu, wsum, off);
    if (ln == 0) s_ws[wid] = wsum;
    __syncthreads();
    if (tid == 0) {
        float t = 0.f;
#pragma unroll
        for (int i = 0; i < 8; i++) t += s_ws[i];
        atomicAdd(&g_acc, (double)t);
    }
}

// ---------------- launch ----------------
extern "C" void kernel_launch(void* const* d_in, const int* in_sizes, int n_in,
                              void* d_out, int out_size) {
    const void*  target = d_in[1];               // int64 or int32 (runtime-detected)
    const float* att    = (const float*)d_in[2]; // (8,4,4096,256)
    (void)in_sizes; (void)n_in; (void)out_size;

    cudaFuncSetAttribute(gemm_kernel, cudaFuncAttributeMaxDynamicSharedMemorySize, SM_TOTAL);

    zero_kernel<<<1, 1>>>();
    detect_kernel<<<1, 256>>>((const unsigned int*)target);
    prep_kernel<<<128, 512>>>(target);
    gemm_kernel<<<2048, 256, SM_TOTAL>>>(att);
    finalize_kernel<<<1, 1>>>((float*)d_out);
}